// round 2
// baseline (speedup 1.0000x reference)
#include <cuda_runtime.h>
#include <math.h>

#define Bb 2
#define Dd 512
#define Cc 512
#define Tt 32
#define TDIMv 1024
#define Hh 8
#define Fv 64
#define NG 32

// ---------------- scratch (device globals; no allocation allowed) ----------------
__device__ float g_stats[Bb*Dd*NG*2];                       // mu, rstd per (bd, group)
__device__ float g_xt[(size_t)Bb*Dd*Tt*Cc];                 // normalized x, [B,D,T,C]
__device__ float g_time[3*Bb*Tt*Cc];                        // [p,b,t,C]
__device__ float g_E[(size_t)3*Bb*Tt*Tt*Cc];                // silu(emb), [p,b,t,s,C]
__device__ float g_R[(size_t)3*Bb*Tt*Tt*Cc];                // rpe bias, [p,b,t,s,C]; p: 0=q,1=k,2=v
__device__ float g_qkv[(size_t)Bb*Dd*Tt*3*Cc];              // [B,D,T,3C]
__device__ float g_attout[(size_t)Bb*Dd*Tt*Cc];             // attention output [B,D,T,C]
__device__ float g_y[(size_t)Bb*Dd*Tt*Cc];                  // proj out + residual [B,D,T,C]

// ---------------- group-norm statistics ----------------
// one block per (b*D + d); 8 warps, each warp reduces 4 groups of 512 contiguous floats
__global__ void gn_stats(const float* __restrict__ x) {
    int bd = blockIdx.x;
    const float4* xp = (const float4*)(x + (size_t)bd * Cc * Tt);
    int warp = threadIdx.x >> 5, lane = threadIdx.x & 31;
    for (int gi = 0; gi < 4; gi++) {
        int g = warp + gi * 8;
        float s = 0.f, ss = 0.f;
        #pragma unroll
        for (int j = 0; j < 4; j++) {
            float4 v = xp[g * 128 + lane + 32 * j];
            s  += v.x + v.y + v.z + v.w;
            ss += v.x * v.x + v.y * v.y + v.z * v.z + v.w * v.w;
        }
        #pragma unroll
        for (int o = 16; o; o >>= 1) {
            s  += __shfl_down_sync(0xffffffffu, s, o);
            ss += __shfl_down_sync(0xffffffffu, ss, o);
        }
        if (lane == 0) {
            float mu  = s * (1.f / 512.f);
            float var = ss * (1.f / 512.f) - mu * mu;
            g_stats[(bd * NG + g) * 2 + 0] = mu;
            g_stats[(bd * NG + g) * 2 + 1] = rsqrtf(var + 1e-5f);
        }
    }
}

// normalize + transpose [C,T] -> [T,C] per (b,d), 32x32 smem tiles
__global__ void gn_norm_transpose(const float* __restrict__ x,
                                  const float* __restrict__ w,
                                  const float* __restrict__ bia) {
    int bd = blockIdx.x, ct = blockIdx.y;
    __shared__ float s[32][33];
    int tx = threadIdx.x, ty = threadIdx.y;
    const float* xb = x + (size_t)bd * Cc * Tt;
    #pragma unroll
    for (int k = 0; k < 4; k++) {
        int cl = ty + 8 * k;
        s[cl][tx] = xb[(ct * 32 + cl) * Tt + tx];
    }
    __syncthreads();
    float* ob = g_xt + (size_t)bd * Tt * Cc;
    int c = ct * 32 + tx;
    int g = c >> 4;
    float mu = g_stats[(bd * NG + g) * 2 + 0];
    float rs = g_stats[(bd * NG + g) * 2 + 1];
    float ww = w[c] * rs;
    float bb = bia[c] - mu * ww;
    #pragma unroll
    for (int k = 0; k < 4; k++) {
        int t = ty + 8 * k;
        ob[t * Cc + c] = s[tx][t] * ww + bb;
    }
}

// ---------------- generic SGEMM: C = A @ W^T + bias (+ resid) ----------------
// A:[M,K] rm, W:[N,K] rm, C:[M,N]. 128x128 tile, BK=8, 256 thr, 8x8 per thread.
// Requires N%128==0, K%8==0; M guarded.
__global__ void __launch_bounds__(256) sgemm_xwT(
    const float* __restrict__ A, const float* __restrict__ W,
    const float* __restrict__ bias, const float* __restrict__ resid,
    float* __restrict__ Cout, int M, int N, int K)
{
    __shared__ float As[8][128];
    __shared__ float Bs[8][128];
    int tid = threadIdx.x;
    int m0 = blockIdx.y * 128, n0 = blockIdx.x * 128;
    int lr = tid >> 1, lc = (tid & 1) * 4;
    const float* Ap = A + (size_t)(m0 + lr) * K + lc;
    const float* Wp = W + (size_t)(n0 + lr) * K + lc;
    bool aok = (m0 + lr) < M;
    float acc[8][8];
    #pragma unroll
    for (int i = 0; i < 8; i++)
        #pragma unroll
        for (int j = 0; j < 8; j++) acc[i][j] = 0.f;
    int tx = tid & 15, ty = tid >> 4;

    for (int k0 = 0; k0 < K; k0 += 8) {
        float4 av = aok ? *(const float4*)(Ap + k0) : make_float4(0.f, 0.f, 0.f, 0.f);
        float4 wv = *(const float4*)(Wp + k0);
        As[lc + 0][lr] = av.x; As[lc + 1][lr] = av.y; As[lc + 2][lr] = av.z; As[lc + 3][lr] = av.w;
        Bs[lc + 0][lr] = wv.x; Bs[lc + 1][lr] = wv.y; Bs[lc + 2][lr] = wv.z; Bs[lc + 3][lr] = wv.w;
        __syncthreads();
        #pragma unroll
        for (int k = 0; k < 8; k++) {
            float a[8], b[8];
            *(float4*)(a)     = *(const float4*)&As[k][ty * 8];
            *(float4*)(a + 4) = *(const float4*)&As[k][ty * 8 + 4];
            *(float4*)(b)     = *(const float4*)&Bs[k][tx * 8];
            *(float4*)(b + 4) = *(const float4*)&Bs[k][tx * 8 + 4];
            #pragma unroll
            for (int i = 0; i < 8; i++)
                #pragma unroll
                for (int j = 0; j < 8; j++) acc[i][j] += a[i] * b[j];
        }
        __syncthreads();
    }

    float bv[8];
    #pragma unroll
    for (int j = 0; j < 8; j++) bv[j] = bias[n0 + tx * 8 + j];
    #pragma unroll
    for (int i = 0; i < 8; i++) {
        int row = m0 + ty * 8 + i;
        if (row < M) {
            float* crow = Cout + (size_t)row * N + n0 + tx * 8;
            if (resid) {
                const float* rrow = resid + (size_t)row * N + n0 + tx * 8;
                #pragma unroll
                for (int j = 0; j < 8; j++) crow[j] = acc[i][j] + bv[j] + rrow[j];
            } else {
                #pragma unroll
                for (int j = 0; j < 8; j++) crow[j] = acc[i][j] + bv[j];
            }
        }
    }
}

// ---------------- RPE: emb = time + feats@dw^T + db; E = silu(emb) ----------------
__global__ void emb_silu(int p, const int* __restrict__ fi,
                         const float* __restrict__ dw, const float* __restrict__ db) {
    int e = blockIdx.x;                 // b*T*T + t*T + s
    int b = e / (Tt * Tt);
    int t = (e / Tt) % Tt;
    int s = e % Tt;
    int d = fi[b * Tt + t] - fi[b * Tt + s];
    float df = (float)d;
    float f0 = log1pf(fmaxf(df, 0.f));
    float f1 = log1pf(fmaxf(-df, 0.f));
    float f2 = (d == 0) ? 1.f : 0.f;
    int c = threadIdx.x;
    float v = g_time[((p * Bb + b) * Tt + t) * Cc + c]
            + f0 * dw[c * 3 + 0] + f1 * dw[c * 3 + 1] + f2 * dw[c * 3 + 2] + db[c];
    float sg = 1.f / (1.f + expf(-v));
    g_E[((size_t)p * Bb * Tt * Tt + e) * Cc + c] = v * sg;
}

// ---------------- fused attention per (b,d,h) ----------------
__global__ void __launch_bounds__(256) attn_kernel(const int* __restrict__ mask) {
    int bdh = blockIdx.x;
    int h = bdh & 7;
    int d = (bdh >> 3) & (Dd - 1);
    int b = bdh >> 12;
    __shared__ float sq[Tt * Fv], sk[Tt * Fv], sv[Tt * Fv];
    __shared__ float satt[Tt][Tt + 1];
    __shared__ int sm[Tt];
    int tid = threadIdx.x;
    const float scale = 0.125f;   // F^-0.5

    const float* qb = g_qkv + (size_t)((b * Dd + d) * Tt) * (3 * Cc) + h * Fv;
    #pragma unroll
    for (int i = 0; i < 8; i++) {
        int e = tid + 256 * i;
        int t = e >> 6, f = e & 63;
        const float* r = qb + t * (3 * Cc) + f;
        sq[e] = r[0] * scale;
        sk[e] = r[Cc];
        sv[e] = r[2 * Cc];
    }
    if (tid < Tt) sm[tid] = mask[b * Tt + tid];
    __syncthreads();

    // logits: q.k + q.Rk[b,t,s,h] + scale*k.Rq[b,s,t,h]
    #pragma unroll
    for (int i = 0; i < 4; i++) {
        int e = tid + 256 * i;
        int t = e >> 5, s = e & 31;
        const float4* rk = (const float4*)(g_R + ((size_t)(1 * Bb + b) * (Tt * Tt) + t * Tt + s) * Cc + h * Fv);
        const float4* rq = (const float4*)(g_R + ((size_t)(0 * Bb + b) * (Tt * Tt) + s * Tt + t) * Cc + h * Fv);
        const float4* q4p = (const float4*)(sq + t * Fv);
        const float4* k4p = (const float4*)(sk + s * Fv);
        float acc = 0.f;
        #pragma unroll
        for (int j = 0; j < 16; j++) {
            float4 q4 = q4p[j], k4 = k4p[j], a4 = rk[j], b4 = rq[j];
            acc += q4.x * (k4.x + a4.x) + scale * k4.x * b4.x;
            acc += q4.y * (k4.y + a4.y) + scale * k4.y * b4.y;
            acc += q4.z * (k4.z + a4.z) + scale * k4.z * b4.z;
            acc += q4.w * (k4.w + a4.w) + scale * k4.w * b4.w;
        }
        satt[t][s] = (sm[t] == sm[s]) ? acc : -1e30f;
    }
    __syncthreads();

    // softmax over s, warp w handles rows 4w..4w+3
    int warp = tid >> 5, lane = tid & 31;
    for (int r = warp * 4; r < warp * 4 + 4; r++) {
        float v = satt[r][lane];
        float m = v;
        #pragma unroll
        for (int o = 16; o; o >>= 1) m = fmaxf(m, __shfl_xor_sync(0xffffffffu, m, o));
        float ev = expf(v - m);
        float ssum = ev;
        #pragma unroll
        for (int o = 16; o; o >>= 1) ssum += __shfl_xor_sync(0xffffffffu, ssum, o);
        satt[r][lane] = ev / ssum;
    }
    __syncthreads();

    // out[t,f] = sum_s att[t,s]*(v[s,f] + Rv[b,t,s,h,f])
    float* ob = g_attout + (size_t)((b * Dd + d) * Tt) * Cc + h * Fv;
    #pragma unroll
    for (int i = 0; i < 8; i++) {
        int e = tid + 256 * i;
        int t = e >> 6, f = e & 63;
        const float* rv = g_R + ((size_t)(2 * Bb + b) * (Tt * Tt) + t * Tt) * Cc + h * Fv + f;
        float acc = 0.f;
        #pragma unroll
        for (int s = 0; s < Tt; s++)
            acc += satt[t][s] * (sv[s * Fv + f] + rv[(size_t)s * Cc]);
        ob[t * Cc + f] = acc;
    }
}

// ---------------- final transpose [B,D,T,C] -> [B,D,C,T] ----------------
__global__ void transpose_out(float* __restrict__ out) {
    int bd = blockIdx.x, ct = blockIdx.y;
    __shared__ float s[32][33];
    int tx = threadIdx.x, ty = threadIdx.y;
    const float* yb = g_y + (size_t)bd * Tt * Cc;
    #pragma unroll
    for (int k = 0; k < 4; k++) {
        int t = ty + 8 * k;
        s[t][tx] = yb[t * Cc + ct * 32 + tx];
    }
    __syncthreads();
    float* ob = out + (size_t)bd * Cc * Tt;
    #pragma unroll
    for (int k = 0; k < 4; k++) {
        int c = ct * 32 + ty + 8 * k;
        ob[c * Tt + tx] = s[tx][ty + 8 * k];
    }
}

// ---------------- launch ----------------
extern "C" void kernel_launch(void* const* d_in, const int* in_sizes, int n_in,
                              void* d_out, int out_size) {
    const float* x      = (const float*)d_in[0];
    const float* temb   = (const float*)d_in[1];
    const int*   fi     = (const int*)d_in[2];
    const int*   amask  = (const int*)d_in[3];
    const float* norm_w = (const float*)d_in[4];
    const float* norm_b = (const float*)d_in[5];
    const float* qkv_w  = (const float*)d_in[6];
    const float* qkv_b  = (const float*)d_in[7];
    const float* proj_w = (const float*)d_in[8];
    const float* proj_b = (const float*)d_in[9];
    float* out = (float*)d_out;

    float *p_xt, *p_time, *p_E, *p_R, *p_qkv, *p_attout, *p_y;
    cudaGetSymbolAddress((void**)&p_xt, g_xt);
    cudaGetSymbolAddress((void**)&p_time, g_time);
    cudaGetSymbolAddress((void**)&p_E, g_E);
    cudaGetSymbolAddress((void**)&p_R, g_R);
    cudaGetSymbolAddress((void**)&p_qkv, g_qkv);
    cudaGetSymbolAddress((void**)&p_attout, g_attout);
    cudaGetSymbolAddress((void**)&p_y, g_y);

    dim3 tb(32, 8);

    // 1. group norm
    gn_stats<<<Bb * Dd, 256>>>(x);
    gn_norm_transpose<<<dim3(Bb * Dd, Cc / 32), tb>>>(x, norm_w, norm_b);

    // 2. RPE pipelines (p: 0=q,1=k,2=v; input indices 10..27)
    for (int p = 0; p < 3; p++) {
        const float* tw  = (const float*)d_in[12 + p * 6];
        const float* tbi = (const float*)d_in[13 + p * 6];
        // time emb: [B*T, TDIM] @ tw^T -> [B*T, C]
        sgemm_xwT<<<dim3(Cc / 128, 1), 256>>>(temb, tw, tbi, nullptr,
                                              p_time + p * Bb * Tt * Cc,
                                              Bb * Tt, Cc, TDIMv);
    }
    for (int p = 0; p < 3; p++) {
        const float* dw = (const float*)d_in[10 + p * 6];
        const float* db = (const float*)d_in[11 + p * 6];
        emb_silu<<<Bb * Tt * Tt, Cc>>>(p, fi, dw, db);
    }
    for (int p = 0; p < 3; p++) {
        const float* ow = (const float*)d_in[14 + p * 6];
        const float* ob = (const float*)d_in[15 + p * 6];
        sgemm_xwT<<<dim3(Cc / 128, (Bb * Tt * Tt) / 128), 256>>>(
            p_E + (size_t)p * Bb * Tt * Tt * Cc, ow, ob, nullptr,
            p_R + (size_t)p * Bb * Tt * Tt * Cc,
            Bb * Tt * Tt, Cc, Cc);
    }

    // 3. QKV GEMM: [32768, 512] @ [512, 1536]^T
    sgemm_xwT<<<dim3((3 * Cc) / 128, (Bb * Dd * Tt) / 128), 256>>>(
        p_xt, qkv_w, qkv_b, nullptr, p_qkv, Bb * Dd * Tt, 3 * Cc, Cc);

    // 4. attention (fused qk + RPE biases + mask + softmax + av + Rv)
    attn_kernel<<<Bb * Dd * Hh, 256>>>(amask);

    // 5. proj GEMM + residual (xt)
    sgemm_xwT<<<dim3(Cc / 128, (Bb * Dd * Tt) / 128), 256>>>(
        p_attout, proj_w, proj_b, p_xt, p_y, Bb * Dd * Tt, Cc, Cc);

    // 6. output transpose
    transpose_out<<<dim3(Bb * Dd, Cc / 32), tb>>>(out);
}

// round 3
// speedup vs baseline: 1.9416x; 1.9416x over previous
#include <cuda_runtime.h>
#include <math.h>
#include <stdint.h>

#define Bb 2
#define Dd 512
#define Cc 512
#define Tt 32
#define TDIMv 1024
#define Hh 8
#define Fv 64
#define NG 32
#define GA 4

// ---------------- scratch (device globals; no allocation allowed) ----------------
__device__ float g_stats[Bb*Dd*NG*2];
__device__ float g_xt[(size_t)Bb*Dd*Tt*Cc];                 // normalized x, [B,D,T,C]
__device__ float g_time[3*Bb*Tt*Cc];                        // [p,b,t,C]
__device__ float g_E[(size_t)3*Bb*Tt*Tt*Cc];                // silu(emb), [p,b,t,s,C]
__device__ float g_R[(size_t)3*Bb*Tt*Tt*Cc];                // rpe bias [p,b,t,s,C]; p: 0=q,1=k,2=v
__device__ float g_qkv[(size_t)Bb*Dd*Tt*3*Cc];              // [B,D,T,3C]
__device__ float g_attout[(size_t)Bb*Dd*Tt*Cc];             // [B,D,T,C]
__device__ float g_y[(size_t)Bb*Dd*Tt*Cc];                  // [B,D,T,C]

// ---------------- group-norm ----------------
__global__ void gn_stats(const float* __restrict__ x) {
    int bd = blockIdx.x;
    const float4* xp = (const float4*)(x + (size_t)bd * Cc * Tt);
    int warp = threadIdx.x >> 5, lane = threadIdx.x & 31;
    for (int gi = 0; gi < 4; gi++) {
        int g = warp + gi * 8;
        float s = 0.f, ss = 0.f;
        #pragma unroll
        for (int j = 0; j < 4; j++) {
            float4 v = xp[g * 128 + lane + 32 * j];
            s  += v.x + v.y + v.z + v.w;
            ss += v.x * v.x + v.y * v.y + v.z * v.z + v.w * v.w;
        }
        #pragma unroll
        for (int o = 16; o; o >>= 1) {
            s  += __shfl_down_sync(0xffffffffu, s, o);
            ss += __shfl_down_sync(0xffffffffu, ss, o);
        }
        if (lane == 0) {
            float mu  = s * (1.f / 512.f);
            float var = ss * (1.f / 512.f) - mu * mu;
            g_stats[(bd * NG + g) * 2 + 0] = mu;
            g_stats[(bd * NG + g) * 2 + 1] = rsqrtf(var + 1e-5f);
        }
    }
}

__global__ void gn_norm_transpose(const float* __restrict__ x,
                                  const float* __restrict__ w,
                                  const float* __restrict__ bia) {
    int bd = blockIdx.x, ct = blockIdx.y;
    __shared__ float s[32][33];
    int tx = threadIdx.x, ty = threadIdx.y;
    const float* xb = x + (size_t)bd * Cc * Tt;
    #pragma unroll
    for (int k = 0; k < 4; k++) {
        int cl = ty + 8 * k;
        s[cl][tx] = xb[(ct * 32 + cl) * Tt + tx];
    }
    __syncthreads();
    float* ob = g_xt + (size_t)bd * Tt * Cc;
    int c = ct * 32 + tx;
    int g = c >> 4;
    float mu = g_stats[(bd * NG + g) * 2 + 0];
    float rs = g_stats[(bd * NG + g) * 2 + 1];
    float ww = w[c] * rs;
    float bb = bia[c] - mu * ww;
    #pragma unroll
    for (int k = 0; k < 4; k++) {
        int t = ty + 8 * k;
        ob[t * Cc + c] = s[tx][t] * ww + bb;
    }
}

// ---------------- tf32 tensor-core GEMM: C = A @ W^T + bias (+ resid) ----------------
// A:[M,K] rm, W:[N,K] rm. BM=BN=128, BK=16, 256 thr (8 warps, 2x4), warp 64x32.
// Requires N%128==0, K%16==0; M guarded.
__device__ __forceinline__ uint32_t f2tf32(float x) {
    uint32_t r; asm("cvt.rna.tf32.f32 %0, %1;" : "=r"(r) : "f"(x)); return r;
}
__device__ __forceinline__ void mma_tf32(float* c, const uint32_t* a, const uint32_t* b) {
    asm volatile("mma.sync.aligned.m16n8k8.row.col.f32.tf32.tf32.f32 "
        "{%0,%1,%2,%3}, {%4,%5,%6,%7}, {%8,%9}, {%0,%1,%2,%3};"
        : "+f"(c[0]), "+f"(c[1]), "+f"(c[2]), "+f"(c[3])
        : "r"(a[0]), "r"(a[1]), "r"(a[2]), "r"(a[3]), "r"(b[0]), "r"(b[1]));
}

#define SROW 136   // smem row stride in words: (8k+m)%32 unique -> conflict-free frags

__global__ void __launch_bounds__(256) gemm_tf32(
    const float* __restrict__ A, const float* __restrict__ W,
    const float* __restrict__ bias, const float* __restrict__ resid,
    float* __restrict__ Cout, int M, int N, int K)
{
    __shared__ uint32_t As[2][16 * SROW];
    __shared__ uint32_t Bs[2][16 * SROW];
    int tid = threadIdx.x;
    int m0 = blockIdx.y * 128, n0 = blockIdx.x * 128;
    int lr = tid >> 1;            // row within tile 0..127
    int lk = (tid & 1) * 8;       // k offset 0 or 8
    const float* Ap = A + (size_t)(m0 + lr) * K + lk;
    const float* Wp = W + (size_t)(n0 + lr) * K + lk;
    bool aok = (m0 + lr) < M;

    float acc[4][4][4];
    #pragma unroll
    for (int i = 0; i < 4; i++)
        #pragma unroll
        for (int j = 0; j < 4; j++)
            #pragma unroll
            for (int q = 0; q < 4; q++) acc[i][j][q] = 0.f;

    int lane = tid & 31, warp = tid >> 5;
    int wm = (warp >> 2) * 64, wn = (warp & 3) * 32;
    int gid = lane >> 2, tig = lane & 3;

    const float4 Z = make_float4(0.f, 0.f, 0.f, 0.f);

    // prologue: tile 0 -> buf 0
    {
        float4 a1 = aok ? *(const float4*)(Ap)     : Z;
        float4 a2 = aok ? *(const float4*)(Ap + 4) : Z;
        float4 w1 = *(const float4*)(Wp);
        float4 w2 = *(const float4*)(Wp + 4);
        uint32_t* Ab = As[0]; uint32_t* Bw = Bs[0];
        Ab[(lk+0)*SROW+lr]=f2tf32(a1.x); Ab[(lk+1)*SROW+lr]=f2tf32(a1.y);
        Ab[(lk+2)*SROW+lr]=f2tf32(a1.z); Ab[(lk+3)*SROW+lr]=f2tf32(a1.w);
        Ab[(lk+4)*SROW+lr]=f2tf32(a2.x); Ab[(lk+5)*SROW+lr]=f2tf32(a2.y);
        Ab[(lk+6)*SROW+lr]=f2tf32(a2.z); Ab[(lk+7)*SROW+lr]=f2tf32(a2.w);
        Bw[(lk+0)*SROW+lr]=f2tf32(w1.x); Bw[(lk+1)*SROW+lr]=f2tf32(w1.y);
        Bw[(lk+2)*SROW+lr]=f2tf32(w1.z); Bw[(lk+3)*SROW+lr]=f2tf32(w1.w);
        Bw[(lk+4)*SROW+lr]=f2tf32(w2.x); Bw[(lk+5)*SROW+lr]=f2tf32(w2.y);
        Bw[(lk+6)*SROW+lr]=f2tf32(w2.z); Bw[(lk+7)*SROW+lr]=f2tf32(w2.w);
    }
    __syncthreads();

    int buf = 0;
    for (int k0 = 16; k0 < K + 16; k0 += 16) {
        float4 pa1, pa2, pw1, pw2;
        bool more = (k0 < K);
        if (more) {
            pa1 = aok ? *(const float4*)(Ap + k0)     : Z;
            pa2 = aok ? *(const float4*)(Ap + k0 + 4) : Z;
            pw1 = *(const float4*)(Wp + k0);
            pw2 = *(const float4*)(Wp + k0 + 4);
        }
        // compute on buf
        const uint32_t* Ab = As[buf];
        const uint32_t* Bw = Bs[buf];
        #pragma unroll
        for (int kk = 0; kk < 16; kk += 8) {
            uint32_t af[4][4], bf[4][2];
            #pragma unroll
            for (int mt = 0; mt < 4; mt++) {
                int r0 = wm + mt * 16 + gid;
                af[mt][0] = Ab[(kk+tig  )*SROW + r0];
                af[mt][1] = Ab[(kk+tig  )*SROW + r0 + 8];
                af[mt][2] = Ab[(kk+tig+4)*SROW + r0];
                af[mt][3] = Ab[(kk+tig+4)*SROW + r0 + 8];
            }
            #pragma unroll
            for (int nt = 0; nt < 4; nt++) {
                int c0 = wn + nt * 8 + gid;
                bf[nt][0] = Bw[(kk+tig  )*SROW + c0];
                bf[nt][1] = Bw[(kk+tig+4)*SROW + c0];
            }
            #pragma unroll
            for (int mt = 0; mt < 4; mt++)
                #pragma unroll
                for (int nt = 0; nt < 4; nt++)
                    mma_tf32(acc[mt][nt], af[mt], bf[nt]);
        }
        if (more) {
            int nb = buf ^ 1;
            uint32_t* An = As[nb]; uint32_t* Bn = Bs[nb];
            An[(lk+0)*SROW+lr]=f2tf32(pa1.x); An[(lk+1)*SROW+lr]=f2tf32(pa1.y);
            An[(lk+2)*SROW+lr]=f2tf32(pa1.z); An[(lk+3)*SROW+lr]=f2tf32(pa1.w);
            An[(lk+4)*SROW+lr]=f2tf32(pa2.x); An[(lk+5)*SROW+lr]=f2tf32(pa2.y);
            An[(lk+6)*SROW+lr]=f2tf32(pa2.z); An[(lk+7)*SROW+lr]=f2tf32(pa2.w);
            Bn[(lk+0)*SROW+lr]=f2tf32(pw1.x); Bn[(lk+1)*SROW+lr]=f2tf32(pw1.y);
            Bn[(lk+2)*SROW+lr]=f2tf32(pw1.z); Bn[(lk+3)*SROW+lr]=f2tf32(pw1.w);
            Bn[(lk+4)*SROW+lr]=f2tf32(pw2.x); Bn[(lk+5)*SROW+lr]=f2tf32(pw2.y);
            Bn[(lk+6)*SROW+lr]=f2tf32(pw2.z); Bn[(lk+7)*SROW+lr]=f2tf32(pw2.w);
            __syncthreads();
            buf = nb;
        }
    }

    // epilogue
    #pragma unroll
    for (int mt = 0; mt < 4; mt++) {
        int row0 = m0 + wm + mt * 16 + gid;
        #pragma unroll
        for (int nt = 0; nt < 4; nt++) {
            int col = n0 + wn + nt * 8 + tig * 2;
            float b0 = bias[col], b1 = bias[col + 1];
            float* c = acc[mt][nt];
            if (row0 < M) {
                float o0 = c[0] + b0, o1 = c[1] + b1;
                float* dst = Cout + (size_t)row0 * N + col;
                if (resid) { const float* rr = resid + (size_t)row0 * N + col; o0 += rr[0]; o1 += rr[1]; }
                dst[0] = o0; dst[1] = o1;
            }
            int row1 = row0 + 8;
            if (row1 < M) {
                float o0 = c[2] + b0, o1 = c[3] + b1;
                float* dst = Cout + (size_t)row1 * N + col;
                if (resid) { const float* rr = resid + (size_t)row1 * N + col; o0 += rr[0]; o1 += rr[1]; }
                dst[0] = o0; dst[1] = o1;
            }
        }
    }
}

// ---------------- RPE: emb = time + feats@dw^T + db; E = silu(emb), all 3 p fused ----------------
__global__ void emb_silu(const int* __restrict__ fi,
                         const float* __restrict__ dw0, const float* __restrict__ db0,
                         const float* __restrict__ dw1, const float* __restrict__ db1,
                         const float* __restrict__ dw2, const float* __restrict__ db2) {
    int e = blockIdx.x;                 // b*T*T + t*T + s
    int p = blockIdx.y;
    const float* dw = (p == 0) ? dw0 : (p == 1) ? dw1 : dw2;
    const float* db = (p == 0) ? db0 : (p == 1) ? db1 : db2;
    int b = e / (Tt * Tt);
    int t = (e / Tt) % Tt;
    int s = e % Tt;
    int d = fi[b * Tt + t] - fi[b * Tt + s];
    float df = (float)d;
    float f0 = log1pf(fmaxf(df, 0.f));
    float f1 = log1pf(fmaxf(-df, 0.f));
    float f2 = (d == 0) ? 1.f : 0.f;
    int c = threadIdx.x;
    float v = g_time[((p * Bb + b) * Tt + t) * Cc + c]
            + f0 * dw[c * 3 + 0] + f1 * dw[c * 3 + 1] + f2 * dw[c * 3 + 2] + db[c];
    float sg = 1.f / (1.f + expf(-v));
    g_E[((size_t)p * Bb * Tt * Tt + e) * Cc + c] = v * sg;
}

// ---------------- fused attention: each block = (b,h) x GA consecutive d ----------------
// amortizes all R (L2) reads GA-fold.
#define QROW 68   // padded row stride (floats): LDS.128 phase-conflict-free for s-indexed rows
#define ATT_SMEM_BYTES ((3*GA*Tt*QROW + GA*Tt*33 + 32) * 4)

__global__ void __launch_bounds__(256) attn_kernel(const int* __restrict__ mask) {
    extern __shared__ float sdyn[];
    int x = blockIdx.x;
    int dg = x & 127;            // Dd/GA = 128
    int h  = (x >> 7) & 7;
    int b  = x >> 10;
    int d0 = dg * GA;
    float* sq   = sdyn;                       // [GA*32][QROW]
    float* sk   = sq + GA * Tt * QROW;
    float* sv   = sk + GA * Tt * QROW;
    float* satt = sv + GA * Tt * QROW;        // [GA*32][33]
    int*   sm   = (int*)(satt + GA * Tt * 33);
    int tid = threadIdx.x;
    const float scale = 0.125f;

    // load q,k,v for GA d's
    const float* base = g_qkv + ((size_t)(b * Dd + d0) * Tt) * (3 * Cc) + h * Fv;
    #pragma unroll
    for (int i = 0; i < 8; i++) {
        int idx = tid + 256 * i;          // 0..2047 float4 slots
        int g  = idx >> 9;
        int t  = (idx >> 4) & 31;
        int f4 = idx & 15;
        const float* r = base + ((size_t)g * Tt + t) * (3 * Cc) + f4 * 4;
        float4 qv = *(const float4*)(r);
        float4 kv = *(const float4*)(r + Cc);
        float4 vv = *(const float4*)(r + 2 * Cc);
        qv.x *= scale; qv.y *= scale; qv.z *= scale; qv.w *= scale;
        *(float4*)(sq + (g * Tt + t) * QROW + f4 * 4) = qv;
        *(float4*)(sk + (g * Tt + t) * QROW + f4 * 4) = kv;
        *(float4*)(sv + (g * Tt + t) * QROW + f4 * 4) = vv;
    }
    if (tid < Tt) sm[tid] = mask[b * Tt + tid];
    __syncthreads();

    // logits: q.k + q.Rk[b,t,s,h] + scale*k.Rq[b,s,t,h], for GA d's sharing the R reads
    const float* Rk = g_R + ((size_t)(1 * Bb + b) * (Tt * Tt)) * Cc + h * Fv;
    const float* Rq = g_R + ((size_t)(0 * Bb + b) * (Tt * Tt)) * Cc + h * Fv;
    #pragma unroll
    for (int i = 0; i < 4; i++) {
        int e = tid + 256 * i;            // (t,s)
        int t = e >> 5, s = e & 31;
        const float4* rk = (const float4*)(Rk + (size_t)(t * Tt + s) * Cc);
        const float4* rq = (const float4*)(Rq + (size_t)(s * Tt + t) * Cc);
        float acc[GA] = {0.f, 0.f, 0.f, 0.f};
        #pragma unroll
        for (int j = 0; j < 16; j++) {
            float4 a4 = rk[j], b4 = rq[j];
            #pragma unroll
            for (int g = 0; g < GA; g++) {
                float4 q4 = *(const float4*)(sq + (g * Tt + t) * QROW + j * 4);
                float4 k4 = *(const float4*)(sk + (g * Tt + s) * QROW + j * 4);
                acc[g] += q4.x * (k4.x + a4.x) + scale * k4.x * b4.x;
                acc[g] += q4.y * (k4.y + a4.y) + scale * k4.y * b4.y;
                acc[g] += q4.z * (k4.z + a4.z) + scale * k4.z * b4.z;
                acc[g] += q4.w * (k4.w + a4.w) + scale * k4.w * b4.w;
            }
        }
        bool ok = (sm[t] == sm[s]);
        #pragma unroll
        for (int g = 0; g < GA; g++)
            satt[(g * Tt + t) * 33 + s] = ok ? acc[g] : -1e30f;
    }
    __syncthreads();

    // softmax: 128 rows (g,t), warp w handles 16 rows
    int warp = tid >> 5, lane = tid & 31;
    for (int r = warp * 16; r < warp * 16 + 16; r++) {
        float v = satt[r * 33 + lane];
        float m = v;
        #pragma unroll
        for (int o = 16; o; o >>= 1) m = fmaxf(m, __shfl_xor_sync(0xffffffffu, m, o));
        float ev = expf(v - m);
        float ssum = ev;
        #pragma unroll
        for (int o = 16; o; o >>= 1) ssum += __shfl_xor_sync(0xffffffffu, ssum, o);
        satt[r * 33 + lane] = ev / ssum;
    }
    __syncthreads();

    // out[t,f] = sum_s att[t,s]*(v[s,f] + Rv[b,t,s,h,f]); Rv shared across GA d's
    const float* Rv = g_R + ((size_t)(2 * Bb + b) * (Tt * Tt)) * Cc + h * Fv;
    float* ob = g_attout + ((size_t)(b * Dd + d0) * Tt) * Cc + h * Fv;
    #pragma unroll
    for (int i = 0; i < 8; i++) {
        int e = tid + 256 * i;            // (t,f) for one g-plane
        int t = e >> 6, f = e & 63;
        const float* rv = Rv + (size_t)(t * Tt) * Cc + f;
        float acc[GA] = {0.f, 0.f, 0.f, 0.f};
        #pragma unroll
        for (int s = 0; s < Tt; s++) {
            float rvv = rv[(size_t)s * Cc];
            #pragma unroll
            for (int g = 0; g < GA; g++)
                acc[g] += satt[(g * Tt + t) * 33 + s] * (sv[(g * Tt + s) * QROW + f] + rvv);
        }
        #pragma unroll
        for (int g = 0; g < GA; g++)
            ob[((size_t)g * Tt + t) * Cc + f] = acc[g];
    }
}

// ---------------- final transpose [B,D,T,C] -> [B,D,C,T] ----------------
__global__ void transpose_out(float* __restrict__ out) {
    int bd = blockIdx.x, ct = blockIdx.y;
    __shared__ float s[32][33];
    int tx = threadIdx.x, ty = threadIdx.y;
    const float* yb = g_y + (size_t)bd * Tt * Cc;
    #pragma unroll
    for (int k = 0; k < 4; k++) {
        int t = ty + 8 * k;
        s[t][tx] = yb[t * Cc + ct * 32 + tx];
    }
    __syncthreads();
    float* ob = out + (size_t)bd * Cc * Tt;
    #pragma unroll
    for (int k = 0; k < 4; k++) {
        int c = ct * 32 + ty + 8 * k;
        ob[c * Tt + tx] = s[tx][ty + 8 * k];
    }
}

// ---------------- launch ----------------
extern "C" void kernel_launch(void* const* d_in, const int* in_sizes, int n_in,
                              void* d_out, int out_size) {
    const float* x      = (const float*)d_in[0];
    const float* temb   = (const float*)d_in[1];
    const int*   fi     = (const int*)d_in[2];
    const int*   amask  = (const int*)d_in[3];
    const float* norm_w = (const float*)d_in[4];
    const float* norm_b = (const float*)d_in[5];
    const float* qkv_w  = (const float*)d_in[6];
    const float* qkv_b  = (const float*)d_in[7];
    const float* proj_w = (const float*)d_in[8];
    const float* proj_b = (const float*)d_in[9];
    float* out = (float*)d_out;

    float *p_xt, *p_time, *p_E, *p_R, *p_qkv, *p_attout, *p_y;
    cudaGetSymbolAddress((void**)&p_xt, g_xt);
    cudaGetSymbolAddress((void**)&p_time, g_time);
    cudaGetSymbolAddress((void**)&p_E, g_E);
    cudaGetSymbolAddress((void**)&p_R, g_R);
    cudaGetSymbolAddress((void**)&p_qkv, g_qkv);
    cudaGetSymbolAddress((void**)&p_attout, g_attout);
    cudaGetSymbolAddress((void**)&p_y, g_y);

    cudaFuncSetAttribute(attn_kernel, cudaFuncAttributeMaxDynamicSharedMemorySize,
                         ATT_SMEM_BYTES);

    dim3 tb(32, 8);

    // 1. group norm
    gn_stats<<<Bb * Dd, 256>>>(x);
    gn_norm_transpose<<<dim3(Bb * Dd, Cc / 32), tb>>>(x, norm_w, norm_b);

    // 2. RPE time GEMMs: [64, 1024] @ [1024, 512]^T (M=64, guarded)
    for (int p = 0; p < 3; p++) {
        const float* tw  = (const float*)d_in[12 + p * 6];
        const float* tbi = (const float*)d_in[13 + p * 6];
        gemm_tf32<<<dim3(Cc / 128, 1), 256>>>(temb, tw, tbi, nullptr,
                                              p_time + p * Bb * Tt * Cc,
                                              Bb * Tt, Cc, TDIMv);
    }
    // 3. emb + silu (all 3 p fused)
    emb_silu<<<dim3(Bb * Tt * Tt, 3), Cc>>>(
        fi,
        (const float*)d_in[10], (const float*)d_in[11],
        (const float*)d_in[16], (const float*)d_in[17],
        (const float*)d_in[22], (const float*)d_in[23]);
    // 4. RPE out GEMMs: [2048, 512] @ [512, 512]^T
    for (int p = 0; p < 3; p++) {
        const float* ow = (const float*)d_in[14 + p * 6];
        const float* ob = (const float*)d_in[15 + p * 6];
        gemm_tf32<<<dim3(Cc / 128, (Bb * Tt * Tt) / 128), 256>>>(
            p_E + (size_t)p * Bb * Tt * Tt * Cc, ow, ob, nullptr,
            p_R + (size_t)p * Bb * Tt * Tt * Cc,
            Bb * Tt * Tt, Cc, Cc);
    }

    // 5. QKV GEMM: [32768, 512] @ [512, 1536]^T
    gemm_tf32<<<dim3((3 * Cc) / 128, (Bb * Dd * Tt) / 128), 256>>>(
        p_xt, qkv_w, qkv_b, nullptr, p_qkv, Bb * Dd * Tt, 3 * Cc, Cc);

    // 6. attention: 2048 blocks, each (b,h) x 4 d's
    attn_kernel<<<Bb * Hh * (Dd / GA), 256, ATT_SMEM_BYTES>>>(amask);

    // 7. proj GEMM + residual
    gemm_tf32<<<dim3(Cc / 128, (Bb * Dd * Tt) / 128), 256>>>(
        p_attout, proj_w, proj_b, p_xt, p_y, Bb * Dd * Tt, Cc, Cc);

    // 8. output transpose
    transpose_out<<<dim3(Bb * Dd, Cc / 32), tb>>>(out);
}

// round 6
// speedup vs baseline: 2.3086x; 1.1890x over previous
#include <cuda_runtime.h>
#include <math.h>
#include <stdint.h>

#define Bb 2
#define Dd 512
#define Cc 512
#define Tt 32
#define TDIMv 1024
#define Hh 8
#define Fv 64
#define NG 32
#define GA 4

// ---------------- scratch (device globals; no allocation allowed) ----------------
__device__ float g_stats[Bb*Dd*NG*2];
__device__ float g_xt[(size_t)Bb*Dd*Tt*Cc];                 // normalized x, [B,D,T,C]
__device__ float g_time[3*Bb*Tt*Cc];                        // [p,b,t,C]
__device__ float g_E[(size_t)3*Bb*Tt*Tt*Cc];                // silu(emb), [p,b,t,s,C]
__device__ float g_R[(size_t)3*Bb*Tt*Tt*Cc];                // rpe bias [p,b,t,s,C]; p: 0=q,1=k,2=v
__device__ float g_qkv[(size_t)Bb*Dd*Tt*3*Cc];              // [B,D,T,3C]
__device__ float g_attout[(size_t)Bb*Dd*Tt*Cc];             // [B,D,T,C]
__device__ float g_y[(size_t)Bb*Dd*Tt*Cc];                  // [B,D,T,C]

// ---------------- group-norm ----------------
__global__ void gn_stats(const float* __restrict__ x) {
    int bd = blockIdx.x;
    const float4* xp = (const float4*)(x + (size_t)bd * Cc * Tt);
    int warp = threadIdx.x >> 5, lane = threadIdx.x & 31;
    for (int gi = 0; gi < 4; gi++) {
        int g = warp + gi * 8;
        float s = 0.f, ss = 0.f;
        #pragma unroll
        for (int j = 0; j < 4; j++) {
            float4 v = xp[g * 128 + lane + 32 * j];
            s  += v.x + v.y + v.z + v.w;
            ss += v.x * v.x + v.y * v.y + v.z * v.z + v.w * v.w;
        }
        #pragma unroll
        for (int o = 16; o; o >>= 1) {
            s  += __shfl_down_sync(0xffffffffu, s, o);
            ss += __shfl_down_sync(0xffffffffu, ss, o);
        }
        if (lane == 0) {
            float mu  = s * (1.f / 512.f);
            float var = ss * (1.f / 512.f) - mu * mu;
            g_stats[(bd * NG + g) * 2 + 0] = mu;
            g_stats[(bd * NG + g) * 2 + 1] = rsqrtf(var + 1e-5f);
        }
    }
}

__global__ void gn_norm_transpose(const float* __restrict__ x,
                                  const float* __restrict__ w,
                                  const float* __restrict__ bia) {
    int bd = blockIdx.x, ct = blockIdx.y;
    __shared__ float s[32][33];
    int tx = threadIdx.x, ty = threadIdx.y;
    const float* xb = x + (size_t)bd * Cc * Tt;
    #pragma unroll
    for (int k = 0; k < 4; k++) {
        int cl = ty + 8 * k;
        s[cl][tx] = xb[(ct * 32 + cl) * Tt + tx];
    }
    __syncthreads();
    float* ob = g_xt + (size_t)bd * Tt * Cc;
    int c = ct * 32 + tx;
    int g = c >> 4;
    float mu = g_stats[(bd * NG + g) * 2 + 0];
    float rs = g_stats[(bd * NG + g) * 2 + 1];
    float ww = w[c] * rs;
    float bb = bia[c] - mu * ww;
    #pragma unroll
    for (int k = 0; k < 4; k++) {
        int t = ty + 8 * k;
        ob[t * Cc + c] = s[tx][t] * ww + bb;
    }
}

// ---------------- time-emb GEMM (M=64, FFMA; tensor tiles are waste here) ----------------
// out[p][m][n] = dot(temb[m,:], W_p[n,:]) + b_p[n];  grid (8 n-tiles, 8 m-tiles, 3 p)
__global__ void __launch_bounds__(256) time_gemm(
    const float* __restrict__ temb,
    const float* __restrict__ w0, const float* __restrict__ w1, const float* __restrict__ w2,
    const float* __restrict__ b0, const float* __restrict__ b1, const float* __restrict__ b2)
{
    int nb = blockIdx.x, mb = blockIdx.y, p = blockIdx.z;
    const float* W  = (p == 0) ? w0 : (p == 1) ? w1 : w2;
    const float* Bi = (p == 0) ? b0 : (p == 1) ? b1 : b2;
    __shared__ float st[8][TDIMv];
    int tid = threadIdx.x;
    const float4* tp = (const float4*)(temb + (size_t)mb * 8 * TDIMv);
    float4* sp = (float4*)&st[0][0];
    #pragma unroll
    for (int i = 0; i < 8; i++) sp[tid + 256 * i] = tp[tid + 256 * i];
    __syncthreads();
    int n  = nb * 64 + (tid & 63);
    int m0 = (tid >> 6) * 2;
    const float4* wp = (const float4*)(W + (size_t)n * TDIMv);
    const float4* t0 = (const float4*)&st[m0][0];
    const float4* t1 = (const float4*)&st[m0 + 1][0];
    float a0 = 0.f, a1 = 0.f;
    #pragma unroll 4
    for (int k = 0; k < TDIMv / 4; k++) {
        float4 w4 = wp[k];
        float4 x0 = t0[k], x1 = t1[k];
        a0 += w4.x * x0.x + w4.y * x0.y + w4.z * x0.z + w4.w * x0.w;
        a1 += w4.x * x1.x + w4.y * x1.y + w4.z * x1.z + w4.w * x1.w;
    }
    float bias = Bi[n];
    int m = mb * 8 + m0;
    g_time[((size_t)p * (Bb * Tt) + m) * Cc + n]     = a0 + bias;
    g_time[((size_t)p * (Bb * Tt) + m + 1) * Cc + n] = a1 + bias;
}

// ---------------- tf32 tensor-core GEMM, cp.async 4-stage pipeline ----------------
// C = A @ W^T + bias (+resid). BM=BN=128, BK=16, 256 thr, warp 64x32.
// M,N multiples of 128; K multiple of 16. z selects (W,bias) triple + A/C offset.
__device__ __forceinline__ void mma_tf32(float* c, const uint32_t* a, const uint32_t* b) {
    asm volatile("mma.sync.aligned.m16n8k8.row.col.f32.tf32.tf32.f32 "
        "{%0,%1,%2,%3}, {%4,%5,%6,%7}, {%8,%9}, {%0,%1,%2,%3};"
        : "+f"(c[0]), "+f"(c[1]), "+f"(c[2]), "+f"(c[3])
        : "r"(a[0]), "r"(a[1]), "r"(a[2]), "r"(a[3]), "r"(b[0]), "r"(b[1]));
}
__device__ __forceinline__ void cpa16(uint32_t s, const void* g) {
    asm volatile("cp.async.cg.shared.global [%0], [%1], 16;" :: "r"(s), "l"(g));
}
__device__ __forceinline__ void cpcommit() { asm volatile("cp.async.commit_group;"); }
template<int Np> __device__ __forceinline__ void cpwait() {
    asm volatile("cp.async.wait_group %0;" :: "n"(Np));
}

#define ASTR 20                    // padded row stride (floats): LDS conflict-free
#define SSTR (128 * ASTR)          // floats per stage per matrix
#define STAGES 4
#define GSMEM (STAGES * SSTR * 2 * 4)

__global__ void __launch_bounds__(256) gemm_tf32(
    const float* __restrict__ A, size_t Asz,
    const float* __restrict__ w0, const float* __restrict__ w1, const float* __restrict__ w2,
    const float* __restrict__ bb0, const float* __restrict__ bb1, const float* __restrict__ bb2,
    const float* __restrict__ resid,
    float* __restrict__ Cout, size_t Csz, int M, int N, int K)
{
    extern __shared__ float smem[];
    float* sA = smem;
    float* sB = smem + STAGES * SSTR;
    int z = blockIdx.z;
    const float* W    = (z == 0) ? w0  : (z == 1) ? w1  : w2;
    const float* bias = (z == 0) ? bb0 : (z == 1) ? bb1 : bb2;
    A += (size_t)z * Asz;
    float* Cz = Cout + (size_t)z * Csz;

    int tid = threadIdx.x;
    int m0 = blockIdx.y * 128, n0 = blockIdx.x * 128;
    int row = tid >> 1;
    int kq  = (tid & 1) * 8;
    const float* Ag = A + (size_t)(m0 + row) * K + kq;
    const float* Wg = W + (size_t)(n0 + row) * K + kq;
    uint32_t sAa = (uint32_t)__cvta_generic_to_shared(sA) + (row * ASTR + kq) * 4;
    uint32_t sBa = (uint32_t)__cvta_generic_to_shared(sB) + (row * ASTR + kq) * 4;
    const uint32_t stageB = SSTR * 4;

    float acc[4][4][4];
    #pragma unroll
    for (int i = 0; i < 4; i++)
        #pragma unroll
        for (int j = 0; j < 4; j++)
            #pragma unroll
            for (int q = 0; q < 4; q++) acc[i][j][q] = 0.f;

    int lane = tid & 31, warp = tid >> 5;
    int wm = (warp >> 2) * 64, wn = (warp & 3) * 32;
    int gid = lane >> 2, tig = lane & 3;
    int NIT = K >> 4;

    #define G_ISSUE(t) { uint32_t bo = ((t) & 3) * stageB;                         \
        const float* ga = Ag + (t) * 16; const float* gb = Wg + (t) * 16;          \
        cpa16(sAa + bo, ga); cpa16(sAa + bo + 16, ga + 4);                         \
        cpa16(sBa + bo, gb); cpa16(sBa + bo + 16, gb + 4); }

    G_ISSUE(0); cpcommit();
    if (NIT > 1) { G_ISSUE(1); } cpcommit();
    if (NIT > 2) { G_ISSUE(2); } cpcommit();

    for (int i = 0; i < NIT; i++) {
        cpwait<2>();
        __syncthreads();
        const uint32_t* Ab = (const uint32_t*)(sA + (i & 3) * SSTR);
        const uint32_t* Bw = (const uint32_t*)(sB + (i & 3) * SSTR);
        #pragma unroll
        for (int kk = 0; kk < 16; kk += 8) {
            uint32_t af[4][4], bf[4][2];
            #pragma unroll
            for (int mt = 0; mt < 4; mt++) {
                int r0 = wm + mt * 16 + gid;
                af[mt][0] = Ab[(r0    ) * ASTR + kk + tig];
                af[mt][1] = Ab[(r0 + 8) * ASTR + kk + tig];
                af[mt][2] = Ab[(r0    ) * ASTR + kk + tig + 4];
                af[mt][3] = Ab[(r0 + 8) * ASTR + kk + tig + 4];
            }
            #pragma unroll
            for (int nt = 0; nt < 4; nt++) {
                int c0 = wn + nt * 8 + gid;
                bf[nt][0] = Bw[c0 * ASTR + kk + tig];
                bf[nt][1] = Bw[c0 * ASTR + kk + tig + 4];
            }
            #pragma unroll
            for (int mt = 0; mt < 4; mt++)
                #pragma unroll
                for (int nt = 0; nt < 4; nt++)
                    mma_tf32(acc[mt][nt], af[mt], bf[nt]);
        }
        if (i + 3 < NIT) { G_ISSUE(i + 3); }
        cpcommit();
    }

    // epilogue (M,N multiples of 128 -> no guards)
    #pragma unroll
    for (int mt = 0; mt < 4; mt++) {
        int r0 = m0 + wm + mt * 16 + gid;
        #pragma unroll
        for (int nt = 0; nt < 4; nt++) {
            int col = n0 + wn + nt * 8 + tig * 2;
            float b0v = bias[col], b1v = bias[col + 1];
            float* c = acc[mt][nt];
            float2 o0 = make_float2(c[0] + b0v, c[1] + b1v);
            float2 o1 = make_float2(c[2] + b0v, c[3] + b1v);
            if (resid) {
                float2 r0v = *(const float2*)(resid + (size_t)r0 * N + col);
                float2 r1v = *(const float2*)(resid + (size_t)(r0 + 8) * N + col);
                o0.x += r0v.x; o0.y += r0v.y; o1.x += r1v.x; o1.y += r1v.y;
            }
            *(float2*)(Cz + (size_t)r0 * N + col) = o0;
            *(float2*)(Cz + (size_t)(r0 + 8) * N + col) = o1;
        }
    }
}

// ---------------- RPE: emb = time + feats@dw^T + db; E = silu(emb) ----------------
__global__ void emb_silu(const int* __restrict__ fi,
                         const float* __restrict__ dw0, const float* __restrict__ db0,
                         const float* __restrict__ dw1, const float* __restrict__ db1,
                         const float* __restrict__ dw2, const float* __restrict__ db2) {
    int e = blockIdx.x;
    int p = blockIdx.y;
    const float* dw = (p == 0) ? dw0 : (p == 1) ? dw1 : dw2;
    const float* db = (p == 0) ? db0 : (p == 1) ? db1 : db2;
    int b = e / (Tt * Tt);
    int t = (e / Tt) % Tt;
    int s = e % Tt;
    int d = fi[b * Tt + t] - fi[b * Tt + s];
    float df = (float)d;
    float f0 = log1pf(fmaxf(df, 0.f));
    float f1 = log1pf(fmaxf(-df, 0.f));
    float f2 = (d == 0) ? 1.f : 0.f;
    int c = threadIdx.x;
    float v = g_time[((p * Bb + b) * Tt + t) * Cc + c]
            + f0 * dw[c * 3 + 0] + f1 * dw[c * 3 + 1] + f2 * dw[c * 3 + 2] + db[c];
    float sg = 1.f / (1.f + expf(-v));
    g_E[((size_t)p * Bb * Tt * Tt + e) * Cc + c] = v * sg;
}

// ---------------- fused attention: block = (b,h) x GA consecutive d; 512 threads ----------------
#define QROW 68
#define ATT_SMEM_BYTES ((3*GA*Tt*QROW + GA*Tt*33 + 32) * 4)

__global__ void __launch_bounds__(512) attn_kernel(const int* __restrict__ mask) {
    extern __shared__ float sdyn[];
    int x = blockIdx.x;
    int dg = x & 127;
    int h  = (x >> 7) & 7;
    int b  = x >> 10;
    int d0 = dg * GA;
    float* sq   = sdyn;
    float* sk   = sq + GA * Tt * QROW;
    float* sv   = sk + GA * Tt * QROW;
    float* satt = sv + GA * Tt * QROW;
    int*   sm   = (int*)(satt + GA * Tt * 33);
    int tid = threadIdx.x;
    const float scale = 0.125f;

    const float* base = g_qkv + ((size_t)(b * Dd + d0) * Tt) * (3 * Cc) + h * Fv;
    #pragma unroll
    for (int i = 0; i < 4; i++) {
        int idx = tid + 512 * i;
        int g  = idx >> 9;
        int t  = (idx >> 4) & 31;
        int f4 = idx & 15;
        const float* r = base + ((size_t)g * Tt + t) * (3 * Cc) + f4 * 4;
        float4 qv = *(const float4*)(r);
        float4 kv = *(const float4*)(r + Cc);
        float4 vv = *(const float4*)(r + 2 * Cc);
        qv.x *= scale; qv.y *= scale; qv.z *= scale; qv.w *= scale;
        *(float4*)(sq + (g * Tt + t) * QROW + f4 * 4) = qv;
        *(float4*)(sk + (g * Tt + t) * QROW + f4 * 4) = kv;
        *(float4*)(sv + (g * Tt + t) * QROW + f4 * 4) = vv;
    }
    if (tid < Tt) sm[tid] = mask[b * Tt + tid];
    __syncthreads();

    const float* Rk = g_R + ((size_t)(1 * Bb + b) * (Tt * Tt)) * Cc + h * Fv;
    const float* Rq = g_R + ((size_t)(0 * Bb + b) * (Tt * Tt)) * Cc + h * Fv;
    #pragma unroll
    for (int i = 0; i < 2; i++) {
        int e = tid + 512 * i;
        int t = e >> 5, s = e & 31;
        const float4* rk = (const float4*)(Rk + (size_t)(t * Tt + s) * Cc);
        const float4* rq = (const float4*)(Rq + (size_t)(s * Tt + t) * Cc);
        float acc[GA] = {0.f, 0.f, 0.f, 0.f};
        #pragma unroll
        for (int j = 0; j < 16; j++) {
            float4 a4 = rk[j], b4 = rq[j];
            #pragma unroll
            for (int g = 0; g < GA; g++) {
                float4 q4 = *(const float4*)(sq + (g * Tt + t) * QROW + j * 4);
                float4 k4 = *(const float4*)(sk + (g * Tt + s) * QROW + j * 4);
                acc[g] += q4.x * (k4.x + a4.x) + scale * k4.x * b4.x;
                acc[g] += q4.y * (k4.y + a4.y) + scale * k4.y * b4.y;
                acc[g] += q4.z * (k4.z + a4.z) + scale * k4.z * b4.z;
                acc[g] += q4.w * (k4.w + a4.w) + scale * k4.w * b4.w;
            }
        }
        bool ok = (sm[t] == sm[s]);
        #pragma unroll
        for (int g = 0; g < GA; g++)
            satt[(g * Tt + t) * 33 + s] = ok ? acc[g] : -1e30f;
    }
    __syncthreads();

    int warp = tid >> 5, lane = tid & 31;
    for (int r = warp * 8; r < warp * 8 + 8; r++) {
        float v = satt[r * 33 + lane];
        float m = v;
        #pragma unroll
        for (int o = 16; o; o >>= 1) m = fmaxf(m, __shfl_xor_sync(0xffffffffu, m, o));
        float ev = expf(v - m);
        float ssum = ev;
        #pragma unroll
        for (int o = 16; o; o >>= 1) ssum += __shfl_xor_sync(0xffffffffu, ssum, o);
        satt[r * 33 + lane] = ev / ssum;
    }
    __syncthreads();

    const float* Rv = g_R + ((size_t)(2 * Bb + b) * (Tt * Tt)) * Cc + h * Fv;
    float* ob = g_attout + ((size_t)(b * Dd + d0) * Tt) * Cc + h * Fv;
    #pragma unroll
    for (int i = 0; i < 4; i++) {
        int e = tid + 512 * i;
        int t = e >> 6, f = e & 63;
        const float* rv = Rv + (size_t)(t * Tt) * Cc + f;
        float acc[GA] = {0.f, 0.f, 0.f, 0.f};
        #pragma unroll
        for (int s = 0; s < Tt; s++) {
            float rvv = rv[(size_t)s * Cc];
            #pragma unroll
            for (int g = 0; g < GA; g++)
                acc[g] += satt[(g * Tt + t) * 33 + s] * (sv[(g * Tt + s) * QROW + f] + rvv);
        }
        #pragma unroll
        for (int g = 0; g < GA; g++)
            ob[((size_t)g * Tt + t) * Cc + f] = acc[g];
    }
}

// ---------------- final transpose [B,D,T,C] -> [B,D,C,T] ----------------
__global__ void transpose_out(float* __restrict__ out) {
    int bd = blockIdx.x, ct = blockIdx.y;
    __shared__ float s[32][33];
    int tx = threadIdx.x, ty = threadIdx.y;
    const float* yb = g_y + (size_t)bd * Tt * Cc;
    #pragma unroll
    for (int k = 0; k < 4; k++) {
        int t = ty + 8 * k;
        s[t][tx] = yb[t * Cc + ct * 32 + tx];
    }
    __syncthreads();
    float* ob = out + (size_t)bd * Cc * Tt;
    #pragma unroll
    for (int k = 0; k < 4; k++) {
        int c = ct * 32 + ty + 8 * k;
        ob[c * Tt + tx] = s[tx][ty + 8 * k];
    }
}

// ---------------- launch ----------------
extern "C" void kernel_launch(void* const* d_in, const int* in_sizes, int n_in,
                              void* d_out, int out_size) {
    const float* x      = (const float*)d_in[0];
    const float* temb   = (const float*)d_in[1];
    const int*   fi     = (const int*)d_in[2];
    const int*   amask  = (const int*)d_in[3];
    const float* norm_w = (const float*)d_in[4];
    const float* norm_b = (const float*)d_in[5];
    const float* qkv_w  = (const float*)d_in[6];
    const float* qkv_b  = (const float*)d_in[7];
    const float* proj_w = (const float*)d_in[8];
    const float* proj_b = (const float*)d_in[9];
    float* out = (float*)d_out;

    float *p_xt, *p_time, *p_E, *p_R, *p_qkv, *p_attout, *p_y;
    cudaGetSymbolAddress((void**)&p_xt, g_xt);
    cudaGetSymbolAddress((void**)&p_time, g_time);
    cudaGetSymbolAddress((void**)&p_E, g_E);
    cudaGetSymbolAddress((void**)&p_R, g_R);
    cudaGetSymbolAddress((void**)&p_qkv, g_qkv);
    cudaGetSymbolAddress((void**)&p_attout, g_attout);
    cudaGetSymbolAddress((void**)&p_y, g_y);

    cudaFuncSetAttribute(attn_kernel, cudaFuncAttributeMaxDynamicSharedMemorySize,
                         ATT_SMEM_BYTES);
    cudaFuncSetAttribute(gemm_tf32, cudaFuncAttributeMaxDynamicSharedMemorySize,
                         GSMEM);

    dim3 tb(32, 8);

    // 1. group norm
    gn_stats<<<Bb * Dd, 256>>>(x);
    gn_norm_transpose<<<dim3(Bb * Dd, Cc / 32), tb>>>(x, norm_w, norm_b);

    // 2. time GEMMs (all 3 p, one launch)
    time_gemm<<<dim3(8, 8, 3), 256>>>(temb,
        (const float*)d_in[12], (const float*)d_in[18], (const float*)d_in[24],
        (const float*)d_in[13], (const float*)d_in[19], (const float*)d_in[25]);

    // 3. emb + silu (all 3 p)
    emb_silu<<<dim3(Bb * Tt * Tt, 3), Cc>>>(
        fi,
        (const float*)d_in[10], (const float*)d_in[11],
        (const float*)d_in[16], (const float*)d_in[17],
        (const float*)d_in[22], (const float*)d_in[23]);

    // 4. QKV GEMM: [32768, 512] @ [512, 1536]^T   (5th launch -> ncu target)
    gemm_tf32<<<dim3((3 * Cc) / 128, (Bb * Dd * Tt) / 128, 1), 256, GSMEM>>>(
        p_xt, 0, qkv_w, qkv_w, qkv_w, qkv_b, qkv_b, qkv_b,
        nullptr, p_qkv, 0, Bb * Dd * Tt, 3 * Cc, Cc);

    // 5. RPE out GEMMs, batched z=3: [2048, 512] @ [512, 512]^T
    gemm_tf32<<<dim3(Cc / 128, (Bb * Tt * Tt) / 128, 3), 256, GSMEM>>>(
        p_E, (size_t)Bb * Tt * Tt * Cc,
        (const float*)d_in[14], (const float*)d_in[20], (const float*)d_in[26],
        (const float*)d_in[15], (const float*)d_in[21], (const float*)d_in[27],
        nullptr, p_R, (size_t)Bb * Tt * Tt * Cc,
        Bb * Tt * Tt, Cc, Cc);

    // 6. attention
    attn_kernel<<<Bb * Hh * (Dd / GA), 512, ATT_SMEM_BYTES>>>(amask);

    // 7. proj GEMM + residual
    gemm_tf32<<<dim3(Cc / 128, (Bb * Dd * Tt) / 128, 1), 256, GSMEM>>>(
        p_attout, 0, proj_w, proj_w, proj_w, proj_b, proj_b, proj_b,
        p_xt, p_y, 0, Bb * Dd * Tt, Cc, Cc);

    // 8. output transpose
    transpose_out<<<dim3(Bb * Dd, Cc / 32), tb>>>(out);
}